// round 16
// baseline (speedup 1.0000x reference)
#include <cuda_runtime.h>
#include <cuda_fp16.h>
#include <mma.h>
#include <math_constants.h>

using namespace nvcuda;

#define N_NODES 50000
#define N_EDGES 1600000
#define IN_DIM  128
#define HEADS   4
#define HID     16
#define HD      64              // HEADS*HID
#define NEG_SLOPE 0.2f

#define SCAN_ELEMS 1024
#define SCAN_BLOCKS ((N_NODES + SCAN_ELEMS - 1) / SCAN_ELEMS)   // 49

// ---------------- scratch (device globals; zero-init at load) ---------------
__device__ __half g_feat_h[N_NODES * HD];   // projected features, fp16
__device__ float  g_el    [N_NODES * HEADS];
__device__ float  g_er    [N_NODES * HEADS];
__device__ int    g_ssrc  [N_EDGES];        // src ids sorted by dst segment
__device__ int    g_rank  [N_EDGES];        // rank of edge within its dst bucket
__device__ int    g_cnt   [SCAN_BLOCKS * SCAN_ELEMS];  // histogram (padded)
__device__ int    g_part  [SCAN_BLOCKS];    // per-block sums
__device__ int    g_flag  [SCAN_BLOCKS];    // lookback flags (reset by k_fill)
__device__ int    g_start [N_NODES + 1];    // segment starts

__device__ __forceinline__ float lrelu(float x) {
    return x > 0.0f ? x : NEG_SLOPE * x;
}

// shared probe: is the raw index array int64 or int32?
__device__ __forceinline__ bool probe_is64(const void* s_raw) {
    __shared__ int is64s;
    if (threadIdx.x == 0) is64s = 1;
    __syncthreads();
    if (threadIdx.x < 256) {
        unsigned long long v = ((const unsigned long long*)s_raw)[threadIdx.x];
        if (v >= (unsigned long long)N_NODES) atomicExch(&is64s, 0);
    }
    __syncthreads();
    return is64s != 0;
}

// load 4 consecutive edge indices starting at e (e % 4 == 0)
__device__ __forceinline__ void load4_idx(const void* raw, bool is64, int e, int* v) {
    if (is64) {
        longlong2 a = ((const longlong2*)raw)[e >> 1];
        longlong2 b = ((const longlong2*)raw)[(e >> 1) + 1];
        v[0] = (int)a.x; v[1] = (int)a.y; v[2] = (int)b.x; v[3] = (int)b.y;
    } else {
        int4 a = ((const int4*)raw)[e >> 2];
        v[0] = a.x; v[1] = a.y; v[2] = a.z; v[3] = a.w;
    }
}

// ---------------- K1: histogram of dst + record per-edge rank (4/thread) ----
__global__ void k_hist(const void* d_raw) {
    const bool is64 = probe_is64(d_raw);
    int e = (blockIdx.x * blockDim.x + threadIdx.x) * 4;
    if (e >= N_EDGES) return;
    int d[4];
    load4_idx(d_raw, is64, e, d);
    int4 r;
    r.x = atomicAdd(&g_cnt[d[0]], 1);
    r.y = atomicAdd(&g_cnt[d[1]], 1);
    r.z = atomicAdd(&g_cnt[d[2]], 1);
    r.w = atomicAdd(&g_cnt[d[3]], 1);
    ((int4*)g_rank)[e >> 2] = r;
}

// ---------------- K2: single-kernel scan (decoupled lookback, grid=49) ------
__global__ void __launch_bounds__(256) k_scan() {
    __shared__ int wsum[8];
    __shared__ int s_off;
    const int b = blockIdx.x, t = threadIdx.x;
    const int lane = t & 31, w = t >> 5;

    int4 v = ((const int4*)g_cnt)[b * 256 + t];
    ((int4*)g_cnt)[b * 256 + t] = make_int4(0, 0, 0, 0);  // self-clean
    int tsum = v.x + v.y + v.z + v.w;

    int inc = tsum;
    #pragma unroll
    for (int o = 1; o < 32; o <<= 1) {
        int x = __shfl_up_sync(0xffffffffu, inc, o);
        if (lane >= o) inc += x;
    }
    if (lane == 31) wsum[w] = inc;
    __syncthreads();
    if (t < 8) {
        int x = wsum[t];
        #pragma unroll
        for (int o = 1; o < 8; o <<= 1) {
            int y = __shfl_up_sync(0xffu, x, o);
            if (t >= o) x += y;
        }
        wsum[t] = x;
    }
    __syncthreads();
    const int blockTotal = wsum[7];

    if (t == 0) {
        ((volatile int*)g_part)[b] = blockTotal;
        __threadfence();
        ((volatile int*)g_flag)[b] = 1;
    }
    if (w == 0) {
        int acc = 0;
        for (int i = lane; i < b; i += 32) {
            while (((volatile int*)g_flag)[i] == 0) { }
            acc += ((volatile int*)g_part)[i];
        }
        #pragma unroll
        for (int o = 16; o > 0; o >>= 1)
            acc += __shfl_xor_sync(0xffffffffu, acc, o);
        if (lane == 0) s_off = acc;
    }
    __syncthreads();
    const int blockOff = s_off;

    if (b == SCAN_BLOCKS - 1 && t == 0)
        g_start[N_NODES] = blockOff + blockTotal;

    int run = blockOff + (inc - tsum) + ((w > 0) ? wsum[w - 1] : 0);
    int base = b * SCAN_ELEMS + t * 4;
    #pragma unroll
    for (int k = 0; k < 4; k++) {
        int idx = base + k;
        if (idx < N_NODES) g_start[idx] = run;
        run += ((const int*)&v)[k];
    }
}

// ---------------- K3: fill sorted edge list — NO atomics, 4 edges/thread ----
__global__ void k_fill(const void* s_raw, const void* d_raw) {
    const bool is64 = probe_is64(d_raw);
    int tidg = blockIdx.x * blockDim.x + threadIdx.x;
    if (tidg < SCAN_BLOCKS) g_flag[tidg] = 0;   // reset lookback flags
    int e = tidg * 4;
    if (e >= N_EDGES) return;
    int s[4], d[4];
    load4_idx(s_raw, is64, e, s);
    load4_idx(d_raw, is64, e, d);
    int4 r = ((const int4*)g_rank)[e >> 2];
    int p0 = g_start[d[0]] + r.x;
    int p1 = g_start[d[1]] + r.y;
    int p2 = g_start[d[2]] + r.z;
    int p3 = g_start[d[3]] + r.w;
    g_ssrc[p0] = s[0];
    g_ssrc[p1] = s[1];
    g_ssrc[p2] = s[2];
    g_ssrc[p3] = s[3];
}

// ---------------- K4: tensor-core GEMM feat = X @ W (wmma, fp16 in) ---------
#define GBM 64
__global__ void __launch_bounds__(256) k_gemm(const float* __restrict__ X,
                                              const float* __restrict__ W,
                                              const float* __restrict__ attn_l,
                                              const float* __restrict__ attn_r) {
    __shared__ __half sX[GBM * IN_DIM];   // 16 KB
    __shared__ __half sW[IN_DIM * HD];    // 16 KB
    __shared__ float  sO[GBM * HD];       // 16 KB
    const int tid  = threadIdx.x;
    const int row0 = blockIdx.x * GBM;

    #pragma unroll
    for (int i = tid; i < GBM * IN_DIM / 4; i += 256) {
        int r = (i * 4) / IN_DIM, c = (i * 4) % IN_DIM;
        int gr = row0 + r;
        float4 v = (gr < N_NODES) ? *(const float4*)&X[gr * IN_DIM + c]
                                  : make_float4(0.f, 0.f, 0.f, 0.f);
        __half2 h0 = __float22half2_rn(make_float2(v.x, v.y));
        __half2 h1 = __float22half2_rn(make_float2(v.z, v.w));
        *(uint2*)&sX[i * 4] = make_uint2(*(unsigned*)&h0, *(unsigned*)&h1);
    }
    #pragma unroll
    for (int i = tid; i < IN_DIM * HD / 4; i += 256) {
        float4 v = *(const float4*)&W[i * 4];
        __half2 h0 = __float22half2_rn(make_float2(v.x, v.y));
        __half2 h1 = __float22half2_rn(make_float2(v.z, v.w));
        *(uint2*)&sW[i * 4] = make_uint2(*(unsigned*)&h0, *(unsigned*)&h1);
    }
    __syncthreads();

    {
        const int w  = tid >> 5;
        const int tr = w >> 2, tc = w & 3;
        wmma::fragment<wmma::accumulator, 16, 16, 16, float> acc0, acc1;
        wmma::fill_fragment(acc0, 0.0f);
        wmma::fill_fragment(acc1, 0.0f);
        #pragma unroll
        for (int k = 0; k < IN_DIM; k += 16) {
            wmma::fragment<wmma::matrix_a, 16, 16, 16, __half, wmma::row_major> fa0, fa1;
            wmma::fragment<wmma::matrix_b, 16, 16, 16, __half, wmma::row_major> fb;
            wmma::load_matrix_sync(fa0, &sX[(tr * 16) * IN_DIM + k], IN_DIM);
            wmma::load_matrix_sync(fa1, &sX[((tr + 2) * 16) * IN_DIM + k], IN_DIM);
            wmma::load_matrix_sync(fb,  &sW[k * HD + tc * 16], HD);
            wmma::mma_sync(acc0, fa0, fb, acc0);
            wmma::mma_sync(acc1, fa1, fb, acc1);
        }
        wmma::store_matrix_sync(&sO[(tr * 16) * HD + tc * 16], acc0, HD, wmma::mem_row_major);
        wmma::store_matrix_sync(&sO[((tr + 2) * 16) * HD + tc * 16], acc1, HD, wmma::mem_row_major);
    }
    __syncthreads();

    {
        const int r = tid >> 2, h = tid & 3;
        const int gr = row0 + r;
        if (gr < N_NODES) {
            float v[16];
            #pragma unroll
            for (int j = 0; j < 4; j++) {
                float4 q = *(const float4*)&sO[r * HD + h * HID + j * 4];
                v[j * 4 + 0] = q.x; v[j * 4 + 1] = q.y;
                v[j * 4 + 2] = q.z; v[j * 4 + 3] = q.w;
            }
            uint4 pk0, pk1;
            #pragma unroll
            for (int j = 0; j < 8; j++) {
                __half2 hh = __float22half2_rn(make_float2(v[j * 2], v[j * 2 + 1]));
                if (j < 4) ((unsigned*)&pk0)[j] = *(unsigned*)&hh;
                else       ((unsigned*)&pk1)[j - 4] = *(unsigned*)&hh;
            }
            *(uint4*)&g_feat_h[gr * HD + h * HID]     = pk0;
            *(uint4*)&g_feat_h[gr * HD + h * HID + 8] = pk1;
            float el = 0.f, er = 0.f;
            #pragma unroll
            for (int j = 0; j < 16; j++) {
                el = fmaf(v[j], attn_l[h * HID + j], el);
                er = fmaf(v[j], attn_r[h * HID + j], er);
            }
            g_el[gr * HEADS + h] = el;
            g_er[gr * HEADS + h] = er;
        }
    }
}

// ---------------- K5: warp-per-node aggregation, 4 edges in flight ----------
__global__ void __launch_bounds__(256) k_agg(const float* __restrict__ bias,
                                             float* __restrict__ out) {
    int warp = (blockIdx.x * blockDim.x + threadIdx.x) >> 5;
    if (warp >= N_NODES) return;
    const int n    = warp;
    const int lane = threadIdx.x & 31;
    const int g    = lane >> 3;
    const int p    = lane & 7;
    const int h    = p >> 1;

    const int beg = g_start[n];
    const int end = g_start[n + 1];

    const float er_h = g_er[n * HEADS + h];

    float acc[8] = {};
    float den = 0.0f;

    int i = beg + g;
    // unroll-4: four edges per group in flight (group stride 4, total 16)
    for (; i + 12 < end; i += 16) {
        int s0 = g_ssrc[i];
        int s1 = g_ssrc[i + 4];
        int s2 = g_ssrc[i + 8];
        int s3 = g_ssrc[i + 12];
        float l0 = g_el[s0 * HEADS + h];
        float l1 = g_el[s1 * HEADS + h];
        float l2 = g_el[s2 * HEADS + h];
        float l3 = g_el[s3 * HEADS + h];
        uint4 k0 = *(const uint4*)&g_feat_h[s0 * HD + p * 8];
        uint4 k1 = *(const uint4*)&g_feat_h[s1 * HD + p * 8];
        uint4 k2 = *(const uint4*)&g_feat_h[s2 * HD + p * 8];
        uint4 k3 = *(const uint4*)&g_feat_h[s3 * HD + p * 8];
        float e0 = __expf(lrelu(l0 + er_h));
        float e1 = __expf(lrelu(l1 + er_h));
        float e2 = __expf(lrelu(l2 + er_h));
        float e3 = __expf(lrelu(l3 + er_h));
        #pragma unroll
        for (int q = 0; q < 4; q++) {
            float2 a = __half22float2(((__half2*)&k0)[q]);
            float2 b = __half22float2(((__half2*)&k1)[q]);
            float2 c = __half22float2(((__half2*)&k2)[q]);
            float2 dd = __half22float2(((__half2*)&k3)[q]);
            acc[q * 2]     = fmaf(a.x, e0, fmaf(b.x, e1, fmaf(c.x, e2, fmaf(dd.x, e3, acc[q * 2]))));
            acc[q * 2 + 1] = fmaf(a.y, e0, fmaf(b.y, e1, fmaf(c.y, e2, fmaf(dd.y, e3, acc[q * 2 + 1]))));
        }
        den += (e0 + e1) + (e2 + e3);
    }
    for (; i < end; i += 4) {
        int s = g_ssrc[i];
        float ee = __expf(lrelu(g_el[s * HEADS + h] + er_h));
        uint4 pk = *(const uint4*)&g_feat_h[s * HD + p * 8];
        #pragma unroll
        for (int q = 0; q < 4; q++) {
            float2 f = __half22float2(((__half2*)&pk)[q]);
            acc[q * 2]     = fmaf(f.x, ee, acc[q * 2]);
            acc[q * 2 + 1] = fmaf(f.y, ee, acc[q * 2 + 1]);
        }
        den += ee;
    }

    #pragma unroll
    for (int k = 0; k < 8; k++) {
        acc[k] += __shfl_xor_sync(0xffffffffu, acc[k], 8);
        acc[k] += __shfl_xor_sync(0xffffffffu, acc[k], 16);
    }
    den += __shfl_xor_sync(0xffffffffu, den, 8);
    den += __shfl_xor_sync(0xffffffffu, den, 16);

    float inv = (den > 0.0f) ? __fdividef(0.25f, den) : 0.0f;
    #pragma unroll
    for (int k = 0; k < 8; k++) acc[k] *= inv;

    #pragma unroll
    for (int k = 0; k < 8; k++) {
        acc[k] += __shfl_xor_sync(0xffffffffu, acc[k], 2);
        acc[k] += __shfl_xor_sync(0xffffffffu, acc[k], 4);
    }

    if (lane < 2) {
        float4 o0, o1;
        #pragma unroll
        for (int k = 0; k < 8; k++) {
            int dd = lane * 8 + k;
            float bm = 0.25f * (bias[dd] + bias[HID + dd]
                              + bias[2 * HID + dd] + bias[3 * HID + dd]);
            if (k < 4) ((float*)&o0)[k] = acc[k] + bm;
            else       ((float*)&o1)[k - 4] = acc[k] + bm;
        }
        *(float4*)&out[n * HID + lane * 8]     = o0;
        *(float4*)&out[n * HID + lane * 8 + 4] = o1;
    }
}

// ---------------- launch ------------------------------------------------------
extern "C" void kernel_launch(void* const* d_in, const int* in_sizes, int n_in,
                              void* d_out, int out_size) {
    const float* features = (const float*)d_in[0];
    const float* W        = (const float*)d_in[1];
    const float* attn_l   = (const float*)d_in[2];
    const float* attn_r   = (const float*)d_in[3];
    const float* bias     = (const float*)d_in[4];
    const void*  src_raw  = d_in[5];
    const void*  dst_raw  = d_in[6];
    float* out = (float*)d_out;

    const int T = 256;

    static cudaStream_t s_side = 0;
    static cudaEvent_t  ev_fork = 0, ev_join = 0;
    if (!s_side) {
        cudaStreamCreateWithFlags(&s_side, cudaStreamNonBlocking);
        cudaEventCreateWithFlags(&ev_fork, cudaEventDisableTiming);
        cudaEventCreateWithFlags(&ev_join, cudaEventDisableTiming);
    }

    // fork: GEMM on side stream; sort chain on main stream
    cudaEventRecord(ev_fork, 0);
    cudaStreamWaitEvent(s_side, ev_fork, 0);
    k_gemm<<<(N_NODES + GBM - 1) / GBM, T, 0, s_side>>>(features, W, attn_l, attn_r);
    cudaEventRecord(ev_join, s_side);

    k_hist<<<(N_EDGES / 4 + T - 1) / T, T>>>(dst_raw);
    k_scan<<<SCAN_BLOCKS, T>>>();
    k_fill<<<(N_EDGES / 4 + T - 1) / T, T>>>(src_raw, dst_raw);

    // join: aggregation needs both branches
    cudaStreamWaitEvent(0, ev_join, 0);
    k_agg<<<(N_NODES * 32 + T - 1) / T, T>>>(bias, out);
}

// round 17
// speedup vs baseline: 1.0960x; 1.0960x over previous
#include <cuda_runtime.h>
#include <cuda_fp16.h>
#include <mma.h>
#include <math_constants.h>

using namespace nvcuda;

#define N_NODES 50000
#define N_EDGES 1600000
#define IN_DIM  128
#define HEADS   4
#define HID     16
#define HD      64              // HEADS*HID
#define NEG_SLOPE 0.2f

#define SCAN_ELEMS 1024
#define SCAN_BLOCKS ((N_NODES + SCAN_ELEMS - 1) / SCAN_ELEMS)   // 49

// ---------------- scratch (device globals; zero-init at load) ---------------
__device__ __half g_feat_h[N_NODES * HD];   // projected features, fp16
__device__ float  g_el    [N_NODES * HEADS];
__device__ float  g_er    [N_NODES * HEADS];
__device__ int    g_ssrc  [N_EDGES];        // src ids sorted by dst segment
__device__ unsigned g_pack[N_EDGES];        // dst | (rank within bucket << 16)
__device__ int    g_cnt   [SCAN_BLOCKS * SCAN_ELEMS];  // histogram (padded)
__device__ int    g_part  [SCAN_BLOCKS];    // per-block sums
__device__ int    g_flag  [SCAN_BLOCKS];    // lookback flags (reset by k_fill)
__device__ int    g_start [N_NODES + 1];    // segment starts

__device__ __forceinline__ float lrelu(float x) {
    return x > 0.0f ? x : NEG_SLOPE * x;
}

// shared probe: is the raw index array int64 or int32?
__device__ __forceinline__ bool probe_is64(const void* raw) {
    __shared__ int is64s;
    if (threadIdx.x == 0) is64s = 1;
    __syncthreads();
    if (threadIdx.x < 256) {
        // int32 data ⇒ upper word of these i64 reads is a random index,
        // guaranteed >= N_NODES among 256 samples.
        unsigned long long v = ((const unsigned long long*)raw)[threadIdx.x];
        if (v >= (unsigned long long)N_NODES) atomicExch(&is64s, 0);
    }
    __syncthreads();
    return is64s != 0;
}

// load 4 consecutive edge indices starting at e (e % 4 == 0)
__device__ __forceinline__ void load4_idx(const void* raw, bool is64, int e, int* v) {
    if (is64) {
        longlong2 a = ((const longlong2*)raw)[e >> 1];
        longlong2 b = ((const longlong2*)raw)[(e >> 1) + 1];
        v[0] = (int)a.x; v[1] = (int)a.y; v[2] = (int)b.x; v[3] = (int)b.y;
    } else {
        int4 a = ((const int4*)raw)[e >> 2];
        v[0] = a.x; v[1] = a.y; v[2] = a.z; v[3] = a.w;
    }
}

// ---------------- K1: histogram of dst + pack dst|rank (4 edges/thread) -----
// dst < 50000 < 2^16; rank = bucket position, max degree ~70 << 2^16.
__global__ void k_hist(const void* d_raw) {
    const bool is64 = probe_is64(d_raw);
    int e = (blockIdx.x * blockDim.x + threadIdx.x) * 4;
    if (e >= N_EDGES) return;
    int d[4];
    load4_idx(d_raw, is64, e, d);
    uint4 pk;
    pk.x = (unsigned)d[0] | ((unsigned)atomicAdd(&g_cnt[d[0]], 1) << 16);
    pk.y = (unsigned)d[1] | ((unsigned)atomicAdd(&g_cnt[d[1]], 1) << 16);
    pk.z = (unsigned)d[2] | ((unsigned)atomicAdd(&g_cnt[d[2]], 1) << 16);
    pk.w = (unsigned)d[3] | ((unsigned)atomicAdd(&g_cnt[d[3]], 1) << 16);
    ((uint4*)g_pack)[e >> 2] = pk;           // coalesced
}

// ---------------- K2: single-kernel scan (decoupled lookback, grid=49) ------
__global__ void __launch_bounds__(256) k_scan() {
    __shared__ int wsum[8];
    __shared__ int s_off;
    const int b = blockIdx.x, t = threadIdx.x;
    const int lane = t & 31, w = t >> 5;

    int4 v = ((const int4*)g_cnt)[b * 256 + t];
    ((int4*)g_cnt)[b * 256 + t] = make_int4(0, 0, 0, 0);  // self-clean
    int tsum = v.x + v.y + v.z + v.w;

    int inc = tsum;
    #pragma unroll
    for (int o = 1; o < 32; o <<= 1) {
        int x = __shfl_up_sync(0xffffffffu, inc, o);
        if (lane >= o) inc += x;
    }
    if (lane == 31) wsum[w] = inc;
    __syncthreads();
    if (t < 8) {
        int x = wsum[t];
        #pragma unroll
        for (int o = 1; o < 8; o <<= 1) {
            int y = __shfl_up_sync(0xffu, x, o);
            if (t >= o) x += y;
        }
        wsum[t] = x;
    }
    __syncthreads();
    const int blockTotal = wsum[7];

    if (t == 0) {
        ((volatile int*)g_part)[b] = blockTotal;
        __threadfence();
        ((volatile int*)g_flag)[b] = 1;
    }
    if (w == 0) {
        int acc = 0;
        for (int i = lane; i < b; i += 32) {
            while (((volatile int*)g_flag)[i] == 0) { }
            acc += ((volatile int*)g_part)[i];
        }
        #pragma unroll
        for (int o = 16; o > 0; o >>= 1)
            acc += __shfl_xor_sync(0xffffffffu, acc, o);
        if (lane == 0) s_off = acc;
    }
    __syncthreads();
    const int blockOff = s_off;

    if (b == SCAN_BLOCKS - 1 && t == 0)
        g_start[N_NODES] = blockOff + blockTotal;

    int run = blockOff + (inc - tsum) + ((w > 0) ? wsum[w - 1] : 0);
    int base = b * SCAN_ELEMS + t * 4;
    #pragma unroll
    for (int k = 0; k < 4; k++) {
        int idx = base + k;
        if (idx < N_NODES) g_start[idx] = run;
        run += ((const int*)&v)[k];
    }
}

// ---------------- K3: fill sorted list — no atomics, reads src + packed -----
__global__ void k_fill(const void* s_raw) {
    const bool is64 = probe_is64(s_raw);
    int tidg = blockIdx.x * blockDim.x + threadIdx.x;
    if (tidg < SCAN_BLOCKS) g_flag[tidg] = 0;   // reset lookback flags
    int e = tidg * 4;
    if (e >= N_EDGES) return;
    int s[4];
    load4_idx(s_raw, is64, e, s);
    uint4 pk = ((const uint4*)g_pack)[e >> 2];
    int p0 = g_start[pk.x & 0xffffu] + (pk.x >> 16);
    int p1 = g_start[pk.y & 0xffffu] + (pk.y >> 16);
    int p2 = g_start[pk.z & 0xffffu] + (pk.z >> 16);
    int p3 = g_start[pk.w & 0xffffu] + (pk.w >> 16);
    g_ssrc[p0] = s[0];
    g_ssrc[p1] = s[1];
    g_ssrc[p2] = s[2];
    g_ssrc[p3] = s[3];
}

// ---------------- K4: tensor-core GEMM (wmma, padded smem — no conflicts) ---
#define GBM 64
#define LDX (IN_DIM + 8)   // 136 halfs
#define LDW (HD + 8)       // 72 halfs
#define LDO (HD + 8)       // 72 floats
__global__ void __launch_bounds__(256) k_gemm(const float* __restrict__ X,
                                              const float* __restrict__ W,
                                              const float* __restrict__ attn_l,
                                              const float* __restrict__ attn_r) {
    __shared__ __half sX[GBM * LDX];      // 17 KB
    __shared__ __half sW[IN_DIM * LDW];   // 18 KB
    __shared__ float  sO[GBM * LDO];      // 18 KB
    const int tid  = threadIdx.x;
    const int row0 = blockIdx.x * GBM;

    // load X tile (fp32 -> fp16), padded rows
    #pragma unroll
    for (int i = tid; i < GBM * IN_DIM / 4; i += 256) {
        int r = (i * 4) / IN_DIM, c = (i * 4) % IN_DIM;
        int gr = row0 + r;
        float4 v = (gr < N_NODES) ? *(const float4*)&X[gr * IN_DIM + c]
                                  : make_float4(0.f, 0.f, 0.f, 0.f);
        __half2 h0 = __float22half2_rn(make_float2(v.x, v.y));
        __half2 h1 = __float22half2_rn(make_float2(v.z, v.w));
        *(uint2*)&sX[r * LDX + c] = make_uint2(*(unsigned*)&h0, *(unsigned*)&h1);
    }
    // load W (128x64), padded rows
    #pragma unroll
    for (int i = tid; i < IN_DIM * HD / 4; i += 256) {
        int r = (i * 4) / HD, c = (i * 4) % HD;
        float4 v = *(const float4*)&W[r * HD + c];
        __half2 h0 = __float22half2_rn(make_float2(v.x, v.y));
        __half2 h1 = __float22half2_rn(make_float2(v.z, v.w));
        *(uint2*)&sW[r * LDW + c] = make_uint2(*(unsigned*)&h0, *(unsigned*)&h1);
    }
    __syncthreads();

    // warp w -> tiles (tr, tc) and (tr+2, tc)
    {
        const int w  = tid >> 5;
        const int tr = w >> 2, tc = w & 3;
        wmma::fragment<wmma::accumulator, 16, 16, 16, float> acc0, acc1;
        wmma::fill_fragment(acc0, 0.0f);
        wmma::fill_fragment(acc1, 0.0f);
        #pragma unroll
        for (int k = 0; k < IN_DIM; k += 16) {
            wmma::fragment<wmma::matrix_a, 16, 16, 16, __half, wmma::row_major> fa0, fa1;
            wmma::fragment<wmma::matrix_b, 16, 16, 16, __half, wmma::row_major> fb;
            wmma::load_matrix_sync(fa0, &sX[(tr * 16) * LDX + k], LDX);
            wmma::load_matrix_sync(fa1, &sX[((tr + 2) * 16) * LDX + k], LDX);
            wmma::load_matrix_sync(fb,  &sW[k * LDW + tc * 16], LDW);
            wmma::mma_sync(acc0, fa0, fb, acc0);
            wmma::mma_sync(acc1, fa1, fb, acc1);
        }
        wmma::store_matrix_sync(&sO[(tr * 16) * LDO + tc * 16], acc0, LDO, wmma::mem_row_major);
        wmma::store_matrix_sync(&sO[((tr + 2) * 16) * LDO + tc * 16], acc1, LDO, wmma::mem_row_major);
    }
    __syncthreads();

    // epilogue: thread = (row r, head h)
    {
        const int r = tid >> 2, h = tid & 3;
        const int gr = row0 + r;
        if (gr < N_NODES) {
            float v[16];
            #pragma unroll
            for (int j = 0; j < 4; j++) {
                float4 q = *(const float4*)&sO[r * LDO + h * HID + j * 4];
                v[j * 4 + 0] = q.x; v[j * 4 + 1] = q.y;
                v[j * 4 + 2] = q.z; v[j * 4 + 3] = q.w;
            }
            uint4 pk0, pk1;
            #pragma unroll
            for (int j = 0; j < 8; j++) {
                __half2 hh = __float22half2_rn(make_float2(v[j * 2], v[j * 2 + 1]));
                if (j < 4) ((unsigned*)&pk0)[j] = *(unsigned*)&hh;
                else       ((unsigned*)&pk1)[j - 4] = *(unsigned*)&hh;
            }
            *(uint4*)&g_feat_h[gr * HD + h * HID]     = pk0;
            *(uint4*)&g_feat_h[gr * HD + h * HID + 8] = pk1;
            float el = 0.f, er = 0.f;
            #pragma unroll
            for (int j = 0; j < 16; j++) {
                el = fmaf(v[j], attn_l[h * HID + j], el);
                er = fmaf(v[j], attn_r[h * HID + j], er);
            }
            g_el[gr * HEADS + h] = el;
            g_er[gr * HEADS + h] = er;
        }
    }
}

// ---------------- K5: warp-per-node aggregation, 2 edges in flight ----------
__global__ void __launch_bounds__(256) k_agg(const float* __restrict__ bias,
                                             float* __restrict__ out) {
    int warp = (blockIdx.x * blockDim.x + threadIdx.x) >> 5;
    if (warp >= N_NODES) return;
    const int n    = warp;
    const int lane = threadIdx.x & 31;
    const int g    = lane >> 3;
    const int p    = lane & 7;
    const int h    = p >> 1;

    const int beg = g_start[n];
    const int end = g_start[n + 1];

    const float er_h = g_er[n * HEADS + h];

    float acc[8] = {};
    float den = 0.0f;

    int i = beg + g;
    for (; i + 4 < end; i += 8) {
        int s0 = g_ssrc[i];
        int s1 = g_ssrc[i + 4];
        float l0 = g_el[s0 * HEADS + h];
        float l1 = g_el[s1 * HEADS + h];
        uint4 pk0 = *(const uint4*)&g_feat_h[s0 * HD + p * 8];
        uint4 pk1 = *(const uint4*)&g_feat_h[s1 * HD + p * 8];
        float ee0 = __expf(lrelu(l0 + er_h));
        float ee1 = __expf(lrelu(l1 + er_h));
        #pragma unroll
        for (int q = 0; q < 4; q++) {
            float2 a = __half22float2(((__half2*)&pk0)[q]);
            float2 b = __half22float2(((__half2*)&pk1)[q]);
            acc[q * 2]     = fmaf(a.x, ee0, fmaf(b.x, ee1, acc[q * 2]));
            acc[q * 2 + 1] = fmaf(a.y, ee0, fmaf(b.y, ee1, acc[q * 2 + 1]));
        }
        den += ee0 + ee1;
    }
    if (i < end) {
        int s = g_ssrc[i];
        float ee = __expf(lrelu(g_el[s * HEADS + h] + er_h));
        uint4 pk = *(const uint4*)&g_feat_h[s * HD + p * 8];
        #pragma unroll
        for (int q = 0; q < 4; q++) {
            float2 f = __half22float2(((__half2*)&pk)[q]);
            acc[q * 2]     = fmaf(f.x, ee, acc[q * 2]);
            acc[q * 2 + 1] = fmaf(f.y, ee, acc[q * 2 + 1]);
        }
        den += ee;
    }

    #pragma unroll
    for (int k = 0; k < 8; k++) {
        acc[k] += __shfl_xor_sync(0xffffffffu, acc[k], 8);
        acc[k] += __shfl_xor_sync(0xffffffffu, acc[k], 16);
    }
    den += __shfl_xor_sync(0xffffffffu, den, 8);
    den += __shfl_xor_sync(0xffffffffu, den, 16);

    float inv = (den > 0.0f) ? __fdividef(0.25f, den) : 0.0f;
    #pragma unroll
    for (int k = 0; k < 8; k++) acc[k] *= inv;

    #pragma unroll
    for (int k = 0; k < 8; k++) {
        acc[k] += __shfl_xor_sync(0xffffffffu, acc[k], 2);
        acc[k] += __shfl_xor_sync(0xffffffffu, acc[k], 4);
    }

    if (lane < 2) {
        float4 o0, o1;
        #pragma unroll
        for (int k = 0; k < 8; k++) {
            int dd = lane * 8 + k;
            float bm = 0.25f * (bias[dd] + bias[HID + dd]
                              + bias[2 * HID + dd] + bias[3 * HID + dd]);
            if (k < 4) ((float*)&o0)[k] = acc[k] + bm;
            else       ((float*)&o1)[k - 4] = acc[k] + bm;
        }
        *(float4*)&out[n * HID + lane * 8]     = o0;
        *(float4*)&out[n * HID + lane * 8 + 4] = o1;
    }
}

// ---------------- launch ------------------------------------------------------
extern "C" void kernel_launch(void* const* d_in, const int* in_sizes, int n_in,
                              void* d_out, int out_size) {
    const float* features = (const float*)d_in[0];
    const float* W        = (const float*)d_in[1];
    const float* attn_l   = (const float*)d_in[2];
    const float* attn_r   = (const float*)d_in[3];
    const float* bias     = (const float*)d_in[4];
    const void*  src_raw  = d_in[5];
    const void*  dst_raw  = d_in[6];
    float* out = (float*)d_out;

    const int T = 256;

    static cudaStream_t s_side = 0;
    static cudaEvent_t  ev_fork = 0, ev_join = 0;
    if (!s_side) {
        cudaStreamCreateWithFlags(&s_side, cudaStreamNonBlocking);
        cudaEventCreateWithFlags(&ev_fork, cudaEventDisableTiming);
        cudaEventCreateWithFlags(&ev_join, cudaEventDisableTiming);
    }

    // fork: GEMM on side stream; sort chain on main stream
    cudaEventRecord(ev_fork, 0);
    cudaStreamWaitEvent(s_side, ev_fork, 0);
    k_gemm<<<(N_NODES + GBM - 1) / GBM, T, 0, s_side>>>(features, W, attn_l, attn_r);
    cudaEventRecord(ev_join, s_side);

    k_hist<<<(N_EDGES / 4 + T - 1) / T, T>>>(dst_raw);
    k_scan<<<SCAN_BLOCKS, T>>>();
    k_fill<<<(N_EDGES / 4 + T - 1) / T, T>>>(src_raw);

    // join: aggregation needs both branches
    cudaStreamWaitEvent(0, ev_join, 0);
    k_agg<<<(N_NODES * 32 + T - 1) / T, T>>>(bias, out);
}